// round 4
// baseline (speedup 1.0000x reference)
#include <cuda_runtime.h>
#include <cstdint>

#define BB    2048
#define SS    201
#define HALF  100
#define DD    128
#define ROWS  (BB*SS)          /* 411648 */
#define A_EL  (ROWS*DD)        /* 52697088 : elems of x_embedding (== pos_enc) */

#define CHASE_BLOCKS 256       /* 8 warps/block * 256 = 2048 batches */
#define EMB_BLOCKS   ((ROWS*32)/256)   /* 51456 */

// scratch: visited_time as int32 for the gather kernel (static device array: allowed)
__device__ int g_visited[ROWS];

// ---------------------------------------------------------------------------
// Kernel A: fused [pointer-chase+top2]  ||  [x_embedding writes].
// Blocks [0, CHASE_BLOCKS): one warp per batch walks the solution cycle.
// Blocks [CHASE_BLOCKS, ...): DRAM-bound emb stores that hide the chase.
//
// Sortable key per stack slot: key = t*512 + (511 - slot)
//   popped/-0.01 -> -1-slot (smaller slot => larger key, = top_k tie-break)
//   slot0 (0.0)  -> 511
//   push t=i+1   -> t*512+511-slot  (> all prior keys, distinct)
// Incremental top2:
//   push: nk > m1 always, displaced key was negative < old m1  => m2=m1; m1=nk
//   pop:  1 shuffle for old key; full 2x redux recompute only if it hit m1/m2
// ---------------------------------------------------------------------------
__global__ void __launch_bounds__(256)
fusedA_kernel(const int*   __restrict__ sol32,
              const float2* __restrict__ x2,
              const float4* __restrict__ W4,
              float4* __restrict__ out_emb,
              float*  __restrict__ out_vt,
              float2* __restrict__ out_t2,
              int write_vt, int write_t2)
{
    __shared__ int s_sol[8][SS + 7];

    if (blockIdx.x < CHASE_BLOCKS) {
        const int warp = threadIdx.x >> 5;
        const int lane = threadIdx.x & 31;
        const int b    = blockIdx.x * 8 + warp;

        // dtype sniff: int64 viewed as int32 has zero odd words; an int32 row
        // has exactly one zero in it, so words 1,3,5 cannot all be zero.
        const bool is_i64 = (sol32[1] == 0) & (sol32[3] == 0) & (sol32[5] == 0);
        if (is_i64) {
            const int* p = sol32 + 2 * b * SS;
            for (int i = lane; i < SS; i += 32) s_sol[warp][i] = p[2 * i];
        } else {
            const int* p = sol32 + b * SS;
            for (int i = lane; i < SS; i += 32) s_sol[warp][i] = p[i];
        }
        __syncwarp();

        const int NEG = (-2147483647 - 1);
        // lane owns slots lane, lane+32, lane+64, lane+96 (valid while <= 100)
        int key0 = (lane == 0) ? 511 : (-1 - lane);
        int key1 = -1 - (lane + 32);
        int key2 = -1 - (lane + 64);
        int key3 = (lane + 96 <= HALF) ? (-1 - (lane + 96)) : NEG;

        int m1 = 511;   // slot 0 (value 0.0)
        int m2 = -2;    // slot 1 (value -0.01)

        int pre = 0;
        const int base = b * SS;

        for (int i = 0; i < SS; i++) {
            const int cur = s_sol[warp][pre];
            pre = cur;
            const int vt = i + 1;

            if (cur != 0) {
                if (cur <= HALF) {
                    // push
                    const int pos = cur;
                    const int nk  = vt * 512 + 511 - pos;
                    if ((pos & 31) == lane) {
                        const int k = pos >> 5;
                        if      (k == 0) key0 = nk;
                        else if (k == 1) key1 = nk;
                        else if (k == 2) key2 = nk;
                        else             key3 = nk;
                    }
                    m2 = m1;
                    m1 = nk;
                } else {
                    // pop
                    const int pos   = cur - HALF;
                    const int knew  = -1 - pos;
                    const int chunk = pos >> 5;
                    const int sl    = pos & 31;
                    const int kc    = (chunk == 0) ? key0 :
                                      (chunk == 1) ? key1 :
                                      (chunk == 2) ? key2 : key3;
                    const int k_old = __shfl_sync(0xffffffffu, kc, sl);
                    if ((pos & 31) == lane) {
                        if      (chunk == 0) key0 = knew;
                        else if (chunk == 1) key1 = knew;
                        else if (chunk == 2) key2 = knew;
                        else                 key3 = knew;
                    }
                    if (k_old == m1 || k_old == m2) {
                        // full top2 recompute (rare): local top2 + 2x redux
                        int a  = max(key0, key1), bl = min(key0, key1);
                        int c  = max(key2, key3), dl = min(key2, key3);
                        int l1 = max(a, c);
                        int l2 = max(min(a, c), max(bl, dl));
                        int M1 = __reduce_max_sync(0xffffffffu, l1);
                        int cand = (l1 == M1) ? l2 : l1;
                        m2 = __reduce_max_sync(0xffffffffu, cand);
                        m1 = M1;
                    } else {
                        m2 = max(m2, knew);   // new negative key may enter 2nd
                    }
                }
            }
            // cur == 0: stacks[0] rewritten with itself -> state unchanged

            if (lane == 0) {
                const int row = base + cur;
                g_visited[row] = vt;
                if (write_vt) out_vt[row] = (float)vt;
                if (write_t2) out_t2[row] = make_float2(
                                  (float)(511 - (m1 & 511)),
                                  (float)(511 - (m2 & 511)));
            }
        }
    } else {
        // x_embedding = x @ W^T : one float4 per thread, streaming stores
        const int gid = (blockIdx.x - CHASE_BLOCKS) * 256 + threadIdx.x;
        const int r   = gid >> 5;
        const int q   = gid & 31;

        const float2 xv  = __ldcs(&x2[r]);
        const float4 w01 = __ldg(&W4[2 * q]);
        const float4 w23 = __ldg(&W4[2 * q + 1]);

        float4 e;
        e.x = xv.x * w01.x + xv.y * w01.y;
        e.y = xv.x * w01.z + xv.y * w01.w;
        e.z = xv.x * w23.x + xv.y * w23.y;
        e.w = xv.x * w23.z + xv.y * w23.w;
        __stcs(&out_emb[r * 32 + q], e);
    }
}

// ---------------------------------------------------------------------------
// Kernel B: pos_enc = pattern[visited % S]. Pure gather + 210 MB stream.
// ---------------------------------------------------------------------------
__global__ void __launch_bounds__(256)
posB_kernel(const float4* __restrict__ patt4,
            float4* __restrict__ out_pos)
{
    const int gid = blockIdx.x * 256 + threadIdx.x;
    const int r   = gid >> 5;
    const int q   = gid & 31;

    const int vt = g_visited[r];                   // 1..201
    const int p  = (vt >= SS) ? (vt - SS) : vt;    // == vt % 201
    __stcs(&out_pos[r * 32 + q], __ldg(&patt4[p * 32 + q]));
}

// ---------------------------------------------------------------------------
extern "C" void kernel_launch(void* const* d_in, const int* in_sizes, int n_in,
                              void* d_out, int out_size)
{
    const float* x   = nullptr;
    const int*   sol = nullptr;
    const float* W   = nullptr;
    const float* pat = nullptr;

    for (int i = 0; i < n_in; i++) {
        switch (in_sizes[i]) {
            case ROWS * 2: x   = (const float*)d_in[i]; break;  // x
            case ROWS:     sol = (const int*)  d_in[i]; break;  // solutions
            case 256:      W   = (const float*)d_in[i]; break;  // W
            case SS * DD:  pat = (const float*)d_in[i]; break;  // pattern
            default: break;
        }
    }

    float* out = (float*)d_out;

    const int write_pos = (out_size >= 2 * A_EL) ? 1 : 0;
    const int write_vt  = (out_size >= 2 * A_EL + ROWS) ? 1 : 0;
    const int write_t2  = (out_size >= 2 * A_EL + 3 * ROWS) ? 1 : 0;

    float*  out_vt = out + (size_t)2 * A_EL;
    float2* out_t2 = (float2*)(out + (size_t)2 * A_EL + ROWS);

    fusedA_kernel<<<CHASE_BLOCKS + EMB_BLOCKS, 256>>>(
        sol, (const float2*)x, (const float4*)W,
        (float4*)out, out_vt, out_t2, write_vt, write_t2);

    if (write_pos)
        posB_kernel<<<EMB_BLOCKS, 256>>>(
            (const float4*)pat, (float4*)(out + (size_t)A_EL));
}